// round 2
// baseline (speedup 1.0000x reference)
#include <cuda_runtime.h>
#include <float.h>

// Problem constants (fixed shapes from reference setup_inputs)
#define B_DIM   64
#define FT      51200          // 80*640 elements per (channel,batch)
#define N_AUX   32
#define WORDS_B 1600           // FT/32 mask words per batch
#define THR     20.0f
#define NPAIR   (N_AUX * B_DIM)    // 2048
#define THREADS 256
#define ITERS   (FT / (THREADS * 4))   // 50, exact

// Strain peak bitmask: 64 batches * 1600 words = 400 KB (L2-resident, reused 32x)
__device__ unsigned g_mask[B_DIM * WORDS_B];
__device__ int g_c1[B_DIM];

__device__ __forceinline__ int warpSum(int v) {
    #pragma unroll
    for (int o = 16; o; o >>= 1) v += __shfl_down_sync(0xffffffffu, v, o);
    return v;
}

// ---------------------------------------------------------------------------
// Kernel 1: strain peak mask + per-batch count. One block per batch.
// Peak rule (flattened over whole [B,F,T]): x[i] > x[i-1] && x[i] > x[i+1]
// && x[i] >= 20, i in [1, N-2]. clamp(min=0) is provably a no-op here.
// ---------------------------------------------------------------------------
__global__ void __launch_bounds__(THREADS) strain_kernel(const float* __restrict__ strain) {
    const int b    = blockIdx.x;
    const int tid  = threadIdx.x;
    const int lane = tid & 31;
    const float*  p  = strain + (size_t)b * FT;
    const float4* p4 = (const float4*)p;

    int cnt = 0;
    #pragma unroll 2
    for (int it = 0; it < ITERS; ++it) {
        const int idx4 = it * THREADS + tid;   // lanes hold consecutive float4s
        const int e    = idx4 * 4;
        float4 v = p4[idx4];

        float prev = __shfl_up_sync(0xffffffffu, v.w, 1);
        if (lane == 0)
            prev = (b == 0 && e == 0) ? FLT_MAX : p[e - 1];   // crosses batch boundary: valid
        float nxt = __shfl_down_sync(0xffffffffu, v.x, 1);
        if (lane == 31)
            nxt = (b == B_DIM - 1 && e + 4 == FT) ? FLT_MAX : p[e + 4];

        unsigned nib = 0;
        nib |= (v.x >= THR && v.x > prev && v.x > v.y) ? 1u : 0u;
        nib |= (v.y >= THR && v.y > v.x  && v.y > v.z) ? 2u : 0u;
        nib |= (v.z >= THR && v.z > v.y  && v.z > v.w) ? 4u : 0u;
        nib |= (v.w >= THR && v.w > v.z  && v.w > nxt) ? 8u : 0u;
        cnt += __popc(nib);

        // pack 8 lanes' nibbles into one 32-bit word (OR-reduce within groups of 8)
        unsigned w = nib << ((lane & 7) * 4);
        w |= __shfl_xor_sync(0xffffffffu, w, 1);
        w |= __shfl_xor_sync(0xffffffffu, w, 2);
        w |= __shfl_xor_sync(0xffffffffu, w, 4);
        if ((lane & 7) == 0)
            g_mask[b * WORDS_B + (idx4 >> 3)] = w;
    }

    __shared__ int sh[THREADS / 32];
    int ws = warpSum(cnt);
    if (lane == 0) sh[tid >> 5] = ws;
    __syncthreads();
    if (tid == 0) {
        int t = 0;
        #pragma unroll
        for (int i = 0; i < THREADS / 32; ++i) t += sh[i];
        g_c1[b] = t;
    }
}

// ---------------------------------------------------------------------------
// Kernel 2: one block per (aux_channel a, batch b). Streams 200KB of qt_aux,
// builds aux peak bits on the fly, ANDs with the L2-resident strain bitmask,
// reduces inter/c2, writes iou and corr directly. No atomics.
// ---------------------------------------------------------------------------
__global__ void __launch_bounds__(THREADS) aux_kernel(const float* __restrict__ aux,
                                                      float* __restrict__ out) {
    const int pair = blockIdx.x;
    const int a    = pair >> 6;       // /64
    const int b    = pair & 63;
    const int tid  = threadIdx.x;
    const int lane = tid & 31;

    const float*  p  = aux + (size_t)a * (B_DIM * (size_t)FT) + (size_t)b * FT;
    const float4* p4 = (const float4*)p;
    const unsigned* mw = g_mask + b * WORDS_B;

    int inter = 0, c2 = 0;
    #pragma unroll 4
    for (int it = 0; it < ITERS; ++it) {
        const int idx4 = it * THREADS + tid;
        const int e    = idx4 * 4;
        float4 v = __ldcs(p4 + idx4);     // streaming: evict-first, keep mask in L2

        float prev = __shfl_up_sync(0xffffffffu, v.w, 1);
        if (lane == 0)
            prev = (b == 0 && e == 0) ? FLT_MAX : __ldcs(p + e - 1);
        float nxt = __shfl_down_sync(0xffffffffu, v.x, 1);
        if (lane == 31)
            nxt = (b == B_DIM - 1 && e + 4 == FT) ? FLT_MAX : __ldcs(p + e + 4);

        unsigned nib = 0;
        nib |= (v.x >= THR && v.x > prev && v.x > v.y) ? 1u : 0u;
        nib |= (v.y >= THR && v.y > v.x  && v.y > v.z) ? 2u : 0u;
        nib |= (v.z >= THR && v.z > v.y  && v.z > v.w) ? 4u : 0u;
        nib |= (v.w >= THR && v.w > v.z  && v.w > nxt) ? 8u : 0u;

        const unsigned sb = (mw[idx4 >> 3] >> ((idx4 & 7) * 4)) & 0xFu;
        c2    += __popc(nib);
        inter += __popc(nib & sb);
    }

    __shared__ int sh1[THREADS / 32], sh2[THREADS / 32];
    int wi = warpSum(inter), wc = warpSum(c2);
    if (lane == 0) { sh1[tid >> 5] = wi; sh2[tid >> 5] = wc; }
    __syncthreads();
    if (tid == 0) {
        int I = 0, C = 0;
        #pragma unroll
        for (int i = 0; i < THREADS / 32; ++i) { I += sh1[i]; C += sh2[i]; }
        const int   c1 = g_c1[b];
        const float If = (float)I;
        const float un = (float)(c1 + C - I);
        float jac, ratio;
        if (I == 0 && (c1 + C - I) == 0) {        // zero-union special case -> 1.0
            jac = 1.0f; ratio = 1.0f;
        } else {
            jac   = If / un;                       // union > 0 here (integers)
            ratio = (c1 > 0) ? If / (float)c1 : 0.0f;  // 0/0 -> nan_to_num -> 0
        }
        out[pair]         = jac;     // iou.reshape(-1)
        out[NPAIR + pair] = ratio;   // corr.reshape(-1), concatenated after
    }
}

// ---------------------------------------------------------------------------
extern "C" void kernel_launch(void* const* d_in, const int* in_sizes, int n_in,
                              void* d_out, int out_size) {
    // metadata order: qt_strain [64,80,640], qt_aux [32,64,80,640]. Pick by size
    // defensively in case of reordering.
    const float* strain;
    const float* aux;
    if (in_sizes[0] == B_DIM * FT) {
        strain = (const float*)d_in[0];
        aux    = (const float*)d_in[1];
    } else {
        strain = (const float*)d_in[1];
        aux    = (const float*)d_in[0];
    }
    float* out = (float*)d_out;

    strain_kernel<<<B_DIM, THREADS>>>(strain);
    aux_kernel<<<NPAIR, THREADS>>>(aux, out);
}

// round 3
// speedup vs baseline: 1.0003x; 1.0003x over previous
#include <cuda_runtime.h>
#include <float.h>

// Fixed shapes from reference setup_inputs
#define B_DIM   64
#define FT      51200              // 80*640 elements per (channel,batch)
#define N_AUX   32
#define WORDS_B 1600               // FT/32 mask words per batch
#define THR     20.0f
#define NPAIR   (N_AUX * B_DIM)    // 2048
#define THREADS 256

// strain kernel decomposition: 10 chunks per batch
#define CHUNKS     10
#define CHUNK_EL   (FT / CHUNKS)           // 5120 elements
#define CHUNK_IT   (CHUNK_EL / (THREADS*4)) // 5 iterations
#define CHUNK_W    (CHUNK_EL / 32)          // 160 mask words

// aux kernel: 50 iters = 10 outer x 5 batched loads
#define UN      5
#define OUTER   (FT / (THREADS * 4 * UN))  // 10

// Strain peak bitmask: 64*1600 words = 400 KB (L2-resident, reused 32x)
__device__ unsigned g_mask[B_DIM * WORDS_B];
__device__ int g_c1p[B_DIM * CHUNKS];      // per-chunk partial counts (no atomics)

__device__ __forceinline__ int warpSum(int v) {
    #pragma unroll
    for (int o = 16; o; o >>= 1) v += __shfl_down_sync(0xffffffffu, v, o);
    return v;
}

__device__ __forceinline__ unsigned peak_nib(float4 v, float prev, float nxt) {
    unsigned nib = 0;
    nib |= (v.x >= THR && v.x > prev && v.x > v.y) ? 1u : 0u;
    nib |= (v.y >= THR && v.y > v.x  && v.y > v.z) ? 2u : 0u;
    nib |= (v.z >= THR && v.z > v.y  && v.z > v.w) ? 4u : 0u;
    nib |= (v.w >= THR && v.w > v.z  && v.w > nxt) ? 8u : 0u;
    return nib;
}

// ---------------------------------------------------------------------------
// Kernel 1: strain peak mask + per-chunk partial counts.
// 640 blocks = 64 batches x 10 chunks. Peaks are over the flattened [B,F,T]
// array (cross batch/chunk boundaries); only global first/last excluded.
// ---------------------------------------------------------------------------
__global__ void __launch_bounds__(THREADS, 4) strain_kernel(const float* __restrict__ strain) {
    const int blk   = blockIdx.x;
    const int b     = blk / CHUNKS;
    const int chunk = blk % CHUNKS;
    const int tid   = threadIdx.x;
    const int lane  = tid & 31;

    const float* pb = strain + (size_t)b * FT;          // batch base
    const float* pc = pb + chunk * CHUNK_EL;            // chunk base
    const float4* p4 = (const float4*)pc;

    int cnt = 0;
    #pragma unroll
    for (int it = 0; it < CHUNK_IT; ++it) {
        const int idx4 = it * THREADS + tid;
        const int e    = chunk * CHUNK_EL + idx4 * 4;   // element index within batch
        float4 v = p4[idx4];

        float prev = __shfl_up_sync(0xffffffffu, v.w, 1);
        if (lane == 0)
            prev = (b == 0 && e == 0) ? FLT_MAX : pb[e - 1];
        float nxt = __shfl_down_sync(0xffffffffu, v.x, 1);
        if (lane == 31)
            nxt = (b == B_DIM - 1 && e + 4 == FT) ? FLT_MAX : pb[e + 4];

        unsigned nib = peak_nib(v, prev, nxt);
        cnt += __popc(nib);

        // pack 8 lanes' nibbles into one 32-bit word
        unsigned w = nib << ((lane & 7) * 4);
        w |= __shfl_xor_sync(0xffffffffu, w, 1);
        w |= __shfl_xor_sync(0xffffffffu, w, 2);
        w |= __shfl_xor_sync(0xffffffffu, w, 4);
        if ((lane & 7) == 0)
            g_mask[b * WORDS_B + chunk * CHUNK_W + (idx4 >> 3)] = w;
    }

    __shared__ int sh[THREADS / 32];
    int ws = warpSum(cnt);
    if (lane == 0) sh[tid >> 5] = ws;
    __syncthreads();
    if (tid == 0) {
        int t = 0;
        #pragma unroll
        for (int i = 0; i < THREADS / 32; ++i) t += sh[i];
        g_c1p[b * CHUNKS + chunk] = t;
    }
}

// ---------------------------------------------------------------------------
// Kernel 2: one block per (aux_channel a, batch b). Streams 200KB of qt_aux
// with 5-deep batched LDG.128 (high MLP), ANDs peak bits against the
// L2-resident strain bitmask, block-reduces, writes results. No atomics.
// ---------------------------------------------------------------------------
__global__ void __launch_bounds__(THREADS, 4) aux_kernel(const float* __restrict__ aux,
                                                         float* __restrict__ out) {
    const int pair = blockIdx.x;
    const int a    = pair >> 6;
    const int b    = pair & 63;
    const int tid  = threadIdx.x;
    const int lane = tid & 31;
    const int msh  = (tid & 7) * 4;        // nibble shift within mask word (constant)

    const float*  p  = aux + (size_t)a * (B_DIM * (size_t)FT) + (size_t)b * FT;
    const float4* p4 = (const float4*)p;
    const unsigned* mw = g_mask + b * WORDS_B;

    int inter = 0, c2 = 0;
    for (int o = 0; o < OUTER; ++o) {
        const int base4 = o * (THREADS * UN) + tid;

        // front-batch UN independent 128-bit streaming loads -> high MLP
        float4 v[UN];
        #pragma unroll
        for (int u = 0; u < UN; ++u)
            v[u] = __ldcs(p4 + base4 + u * THREADS);

        unsigned sb[UN];
        #pragma unroll
        for (int u = 0; u < UN; ++u)
            sb[u] = mw[(base4 + u * THREADS) >> 3];

        #pragma unroll
        for (int u = 0; u < UN; ++u) {
            const int idx4 = base4 + u * THREADS;
            const int e    = idx4 * 4;

            float prev = __shfl_up_sync(0xffffffffu, v[u].w, 1);
            if (lane == 0)
                prev = (b == 0 && e == 0) ? FLT_MAX : __ldcs(p + e - 1);
            float nxt = __shfl_down_sync(0xffffffffu, v[u].x, 1);
            if (lane == 31)
                nxt = (b == B_DIM - 1 && e + 4 == FT) ? FLT_MAX : __ldcs(p + e + 4);

            unsigned nib = peak_nib(v[u], prev, nxt);
            c2    += __popc(nib);
            inter += __popc(nib & ((sb[u] >> msh) & 0xFu));
        }
    }

    __shared__ int sh1[THREADS / 32], sh2[THREADS / 32];
    int wi = warpSum(inter), wc = warpSum(c2);
    if (lane == 0) { sh1[tid >> 5] = wi; sh2[tid >> 5] = wc; }
    __syncthreads();
    if (tid == 0) {
        int I = 0, C = 0;
        #pragma unroll
        for (int i = 0; i < THREADS / 32; ++i) { I += sh1[i]; C += sh2[i]; }
        int c1 = 0;
        #pragma unroll
        for (int i = 0; i < CHUNKS; ++i) c1 += g_c1p[b * CHUNKS + i];

        const float If = (float)I;
        const int   u  = c1 + C - I;
        float jac, ratio;
        if (I == 0 && u == 0) {                     // zero-union -> 1.0
            jac = 1.0f; ratio = 1.0f;
        } else {
            jac   = If / (float)u;                  // union > 0 here
            ratio = (c1 > 0) ? If / (float)c1 : 0.0f;  // 0/0 -> nan_to_num -> 0
        }
        out[pair]         = jac;     // iou.reshape(-1)
        out[NPAIR + pair] = ratio;   // corr.reshape(-1)
    }
}

// ---------------------------------------------------------------------------
extern "C" void kernel_launch(void* const* d_in, const int* in_sizes, int n_in,
                              void* d_out, int out_size) {
    const float* strain;
    const float* aux;
    if (in_sizes[0] == B_DIM * FT) {
        strain = (const float*)d_in[0];
        aux    = (const float*)d_in[1];
    } else {
        strain = (const float*)d_in[1];
        aux    = (const float*)d_in[0];
    }
    float* out = (float*)d_out;

    strain_kernel<<<B_DIM * CHUNKS, THREADS>>>(strain);
    aux_kernel<<<NPAIR, THREADS>>>(aux, out);
}